// round 12
// baseline (speedup 1.0000x reference)
#include <cuda_runtime.h>
#include <cuda_bf16.h>
#include <cstdint>

#define TOKENS 32768
#define DMODEL 4096
#define NEXP   64
#define BM     128
#define BK     16
#define XPITCH 132               // xs row pitch (floats): 16B-aligned rows, 2-way STS max
#define WPITCH 132               // wdup row pitch (floats): same properties
#define NSLAB  (DMODEL / BK)     // 256
#define NBLK_B (TOKENS / 256)    // 128 blocks in the gate kernel
#define MAXR   256               // rescue list capacity
#define EPS_MARGIN 2e-4f         // rescue threshold on noisy top1-top2 margin

// Scratch (no allocations allowed)
__device__ float g_h[TOKENS * NEXP];
__device__ float g_imp[NBLK_B * NEXP];
__device__ int   g_load[NBLK_B * NEXP];
__device__ int   g_rescue_cnt;
__device__ int   g_rescue_list[MAXR];
__device__ int   g_load_delta[NEXP];

// ---- packed f32x2 helpers (FFMA2 — only reachable via PTX fma.rn.f32x2) ----
static __device__ __forceinline__ void unpack2(unsigned long long v, float& lo, float& hi) {
    asm("mov.b64 {%0, %1}, %2;" : "=f"(lo), "=f"(hi) : "l"(v));
}
static __device__ __forceinline__ void ffma2(unsigned long long& d,
                                             unsigned long long a,
                                             unsigned long long b) {
    asm("fma.rn.f32x2 %0, %1, %2, %0;" : "+l"(d) : "l"(a), "l"(b));
}

// ============================================================================
// Kernel A: h = tanh(x @ w1^T)   [32768,4096] x [64,4096]^T -> [32768,64]
// 256 threads/CTA, tile 128 tokens x 64 experts, per-thread 8 tok x 4 exp
// (32 independent FFMA2/k from only 4 LDS.128 — w is stored pre-duplicated
// in shared so packed operands load directly, no register packing movs).
//   tid&15  -> token group (8 consecutive tokens)
//   tid>>4  -> expert group (4 experts)
// ============================================================================
__global__ void __launch_bounds__(256, 2)
gemm1_tanh(const float* __restrict__ x, const float* __restrict__ w1) {
    __shared__ __align__(16) float xs[BK][XPITCH];    // xs[k][token]
    __shared__ __align__(16) float wdup[BK][WPITCH];  // wdup[k][2e]=wdup[k][2e+1]=w[k][e]

    const int tid = threadIdx.x;
    const int bm  = blockIdx.x * BM;
    const int tg  = tid & 15;              // token group: tokens tg*8 .. tg*8+7
    const int e0  = (tid >> 4) * 4;        // experts e0 .. e0+3

    // rescue-state reset (gate runs strictly after gemm1 in stream order)
    if (blockIdx.x == 0) {
        if (tid == 0) g_rescue_cnt = 0;
        if (tid < NEXP) g_load_delta[tid] = 0;
    }

    unsigned long long acc[4][4];          // [token-pair][expert]
#pragma unroll
    for (int p = 0; p < 4; p++)
#pragma unroll
        for (int e = 0; e < 4; e++) acc[p][e] = 0ull;

    // loader coords
    const int lrow = tid >> 2;             // 0..63
    const int lc4  = tid & 3;              // k-chunk (4 floats)

    // ---- prologue: load slab 0 ----
    float4 xr[2], wr;
#pragma unroll
    for (int i = 0; i < 2; i++)
        xr[i] = *reinterpret_cast<const float4*>(
            &x[(size_t)(bm + lrow + 64 * i) * DMODEL + lc4 * 4]);
    wr = *reinterpret_cast<const float4*>(&w1[(size_t)lrow * DMODEL + lc4 * 4]);

#pragma unroll 1
    for (int sl = 0; sl < NSLAB; sl++) {
        if (sl) __syncthreads();           // all warps done reading previous slab

        // transpose-store x slab
#pragma unroll
        for (int i = 0; i < 2; i++) {
            const int row = lrow + 64 * i;
            xs[lc4 * 4 + 0][row] = xr[i].x;
            xs[lc4 * 4 + 1][row] = xr[i].y;
            xs[lc4 * 4 + 2][row] = xr[i].z;
            xs[lc4 * 4 + 3][row] = xr[i].w;
        }
        // duplicated-store w slab (each value twice -> f32x2-ready operands)
        {
            const int e2 = lrow * 2;
            *reinterpret_cast<float2*>(&wdup[lc4 * 4 + 0][e2]) = make_float2(wr.x, wr.x);
            *reinterpret_cast<float2*>(&wdup[lc4 * 4 + 1][e2]) = make_float2(wr.y, wr.y);
            *reinterpret_cast<float2*>(&wdup[lc4 * 4 + 2][e2]) = make_float2(wr.z, wr.z);
            *reinterpret_cast<float2*>(&wdup[lc4 * 4 + 3][e2]) = make_float2(wr.w, wr.w);
        }
        __syncthreads();

        // prefetch next slab (overlaps compute below)
        if (sl + 1 < NSLAB) {
            const int kk = (sl + 1) * BK;
#pragma unroll
            for (int i = 0; i < 2; i++)
                xr[i] = *reinterpret_cast<const float4*>(
                    &x[(size_t)(bm + lrow + 64 * i) * DMODEL + kk + lc4 * 4]);
            wr = *reinterpret_cast<const float4*>(
                &w1[(size_t)lrow * DMODEL + kk + lc4 * 4]);
        }

#pragma unroll
        for (int k = 0; k < BK; k++) {
            // 8 consecutive tokens = 4 f32x2 pairs (two conflict-free LDS.128)
            const ulonglong2 xa = *reinterpret_cast<const ulonglong2*>(&xs[k][tg * 8]);
            const ulonglong2 xb = *reinterpret_cast<const ulonglong2*>(&xs[k][tg * 8 + 4]);
            // 4 duplicated experts = 4 f32x2 operands (two broadcast LDS.128)
            const ulonglong2 w01 = *reinterpret_cast<const ulonglong2*>(&wdup[k][e0 * 2]);
            const ulonglong2 w23 = *reinterpret_cast<const ulonglong2*>(&wdup[k][e0 * 2 + 4]);
#pragma unroll
            for (int p = 0; p < 1; p++) { } // (keep compiler from reordering barriers)
            ffma2(acc[0][0], xa.x, w01.x); ffma2(acc[0][1], xa.x, w01.y);
            ffma2(acc[0][2], xa.x, w23.x); ffma2(acc[0][3], xa.x, w23.y);
            ffma2(acc[1][0], xa.y, w01.x); ffma2(acc[1][1], xa.y, w01.y);
            ffma2(acc[1][2], xa.y, w23.x); ffma2(acc[1][3], xa.y, w23.y);
            ffma2(acc[2][0], xb.x, w01.x); ffma2(acc[2][1], xb.x, w01.y);
            ffma2(acc[2][2], xb.x, w23.x); ffma2(acc[2][3], xb.x, w23.y);
            ffma2(acc[3][0], xb.y, w01.x); ffma2(acc[3][1], xb.y, w01.y);
            ffma2(acc[3][2], xb.y, w23.x); ffma2(acc[3][3], xb.y, w23.y);
        }
    }

    // ---- epilogue: tanh + store 8 tokens x 4 experts ----
#pragma unroll
    for (int p = 0; p < 4; p++) {
        float lo[4], hi[4];
#pragma unroll
        for (int e = 0; e < 4; e++) unpack2(acc[p][e], lo[e], hi[e]);
        const int t0 = bm + tg * 8 + 2 * p;
        *reinterpret_cast<float4*>(&g_h[(size_t)t0 * NEXP + e0]) =
            make_float4(tanhf(lo[0]), tanhf(lo[1]), tanhf(lo[2]), tanhf(lo[3]));
        *reinterpret_cast<float4*>(&g_h[(size_t)(t0 + 1) * NEXP + e0]) =
            make_float4(tanhf(hi[0]), tanhf(hi[1]), tanhf(hi[2]), tanhf(hi[3]));
    }
}

// ============================================================================
// Kernel B: logits = h @ w2^T; softmax; argmax(logits+noise); near-tie tokens
// flagged for fp64 rescue; deterministic block partials (no float atomics).
// ============================================================================
__global__ void __launch_bounds__(256)
gate_kernel(const float* __restrict__ w2, const float* __restrict__ noise,
            float* __restrict__ out) {
    __shared__ float w2s[NEXP][NEXP];
    __shared__ float s_imp[8][NEXP];
    __shared__ int   s_load[NEXP];

    const int tid  = threadIdx.x;
    const int warp = tid >> 5;

    for (int i = tid; i < NEXP * NEXP; i += 256) w2s[i >> 6][i & 63] = w2[i];
    if (tid < NEXP) s_load[tid] = 0;
    __syncthreads();

    const int t = blockIdx.x * 256 + tid;

    float l[NEXP];
#pragma unroll
    for (int e = 0; e < NEXP; e++) l[e] = 0.f;

    const float4* hrow = reinterpret_cast<const float4*>(&g_h[(size_t)t * NEXP]);
#pragma unroll 2
    for (int j4 = 0; j4 < 16; j4++) {
        float4 hv = hrow[j4];
#pragma unroll
        for (int e = 0; e < NEXP; e++) {
            l[e] += hv.x * w2s[e][4 * j4 + 0] + hv.y * w2s[e][4 * j4 + 1] +
                    hv.z * w2s[e][4 * j4 + 2] + hv.w * w2s[e][4 * j4 + 3];
        }
    }

    float maxl = l[0];
#pragma unroll
    for (int e = 1; e < NEXP; e++) maxl = fmaxf(maxl, l[e]);

    // argmax of logits + gumbel noise, tracking top-2 margin for rescue
    const float4* nrow = reinterpret_cast<const float4*>(&noise[(size_t)t * NEXP]);
    float best = -3.402823466e38f, second = -3.402823466e38f;
    int   bi   = 0;
#pragma unroll
    for (int e4 = 0; e4 < 16; e4++) {
        float4 nv = nrow[e4];
        float v;
#define STEP(COMP, OFF)                                                        \
        v = l[4 * e4 + OFF] + nv.COMP;                                         \
        if (v > best) { second = best; best = v; bi = 4 * e4 + OFF; }          \
        else if (v > second) { second = v; }
        STEP(x, 0) STEP(y, 1) STEP(z, 2) STEP(w, 3)
#undef STEP
    }
    if (best - second < EPS_MARGIN) {
        int idx = atomicAdd(&g_rescue_cnt, 1);
        if (idx < MAXR) g_rescue_list[idx] = t;
    }

    float Z = 0.f;
#pragma unroll
    for (int e = 0; e < NEXP; e++) Z += expf(l[e] - maxl);
    const float inv = 1.0f / Z;

#pragma unroll
    for (int e = 0; e < NEXP; e++) {
        float v = expf(l[e] - maxl) * inv;
        v += __shfl_xor_sync(0xffffffffu, v, 16);
        v += __shfl_xor_sync(0xffffffffu, v, 8);
        v += __shfl_xor_sync(0xffffffffu, v, 4);
        v += __shfl_xor_sync(0xffffffffu, v, 2);
        v += __shfl_xor_sync(0xffffffffu, v, 1);
        if ((tid & 31) == 0) s_imp[warp][e] = v;
    }

    atomicAdd(&s_load[bi], 1);   // integer atomics: deterministic

    out[t]          = (float)bi;
    out[TOKENS + t] = best;

    __syncthreads();
    if (tid < NEXP) {
        float s = 0.f;
#pragma unroll
        for (int w = 0; w < 8; w++) s += s_imp[w][tid];
        g_imp[blockIdx.x * NEXP + tid]  = s;
        g_load[blockIdx.x * NEXP + tid] = s_load[tid];
    }
}

// ============================================================================
// Rescue: recompute flagged tokens' gate in fp64 straight from inputs,
// patch indices/scores, accumulate integer load deltas. Deterministic.
// ============================================================================
__global__ void __launch_bounds__(256)
rescue_kernel(const float* __restrict__ x, const float* __restrict__ w1,
              const float* __restrict__ w2, const float* __restrict__ noise,
              float* __restrict__ out) {
    int cnt = g_rescue_cnt;
    if (cnt > MAXR) cnt = MAXR;
    if ((int)blockIdx.x >= cnt) return;
    const int t   = g_rescue_list[blockIdx.x];
    const int tid = threadIdx.x;
    const int j   = tid >> 2;     // expert for layer-1 row
    const int q   = tid & 3;      // k-quarter

    __shared__ double pz[NEXP][4];
    __shared__ double hs[NEXP];
    __shared__ double lv[NEXP];

    const float* xr = x + (size_t)t * DMODEL;
    const float* wr = w1 + (size_t)j * DMODEL;
    double partial = 0.0;
    const int k0 = q * (DMODEL / 4);
#pragma unroll 4
    for (int k = k0; k < k0 + DMODEL / 4; k++)
        partial += (double)xr[k] * (double)wr[k];
    pz[j][q] = partial;
    __syncthreads();

    if (q == 0) {
        double z = ((pz[j][0] + pz[j][1]) + pz[j][2]) + pz[j][3];
        hs[j] = tanh(z);
    }
    __syncthreads();

    if (tid < NEXP) {
        double s = 0.0;
        for (int jj = 0; jj < NEXP; jj++) s += hs[jj] * (double)w2[tid * NEXP + jj];
        lv[tid] = s + (double)noise[(size_t)t * NEXP + tid];
    }
    __syncthreads();

    if (tid == 0) {
        double bv = lv[0];
        int bi = 0;
        for (int e = 1; e < NEXP; e++)
            if (lv[e] > bv) { bv = lv[e]; bi = e; }
        const int old = (int)out[t];
        if (old != bi) {
            atomicAdd(&g_load_delta[old], -1);
            atomicAdd(&g_load_delta[bi], 1);
            out[t] = (float)bi;
        }
        out[TOKENS + t] = (float)bv;
    }
}

// ============================================================================
// Kernel C: finalize — 256 threads, fixed-order 2-stage reduction
// (4 partials of 32 blocks each, then fixed combine) -> deterministic.
// ============================================================================
__global__ void __launch_bounds__(256)
finalize_kernel(float* __restrict__ out) {
    __shared__ float pimp[4][NEXP];
    __shared__ int   pld[4][NEXP];
    __shared__ float red[NEXP];

    const int tid = threadIdx.x;
    const int e   = tid & 63;
    const int q   = tid >> 6;     // 0..3

    float s  = 0.f;
    int   ld = 0;
    for (int b = q * 32; b < q * 32 + 32; b++) {
        s  += g_imp[b * NEXP + e];
        ld += g_load[b * NEXP + e];
    }
    pimp[q][e] = s;
    pld[q][e]  = ld;
    __syncthreads();

    if (tid < NEXP) {
        const float si = ((pimp[0][tid] + pimp[1][tid]) + pimp[2][tid]) + pimp[3][tid];
        const int   li = pld[0][tid] + pld[1][tid] + pld[2][tid] + pld[3][tid]
                         + g_load_delta[tid];
        const float imp_mean  = si * (1.0f / TOKENS);
        const float load_mean = (float)li * (1.0f / TOKENS);
        out[2 * TOKENS + 1 + tid]        = load_mean;
        out[2 * TOKENS + 1 + NEXP + tid] = imp_mean;
        red[tid] = imp_mean * load_mean;
    }
    __syncthreads();
    if (tid == 0) {
        float a = 0.f;
        for (int i = 0; i < NEXP; i++) a += red[i];
        out[2 * TOKENS] = (float)NEXP * a * 0.1f;
    }
}

extern "C" void kernel_launch(void* const* d_in, const int* in_sizes, int n_in,
                              void* d_out, int out_size) {
    const float* x     = (const float*)d_in[0];
    const float* w1    = (const float*)d_in[1];
    const float* w2    = (const float*)d_in[2];
    const float* noise = (const float*)d_in[3];
    float* out = (float*)d_out;

    gemm1_tanh<<<TOKENS / BM, 256>>>(x, w1);
    gate_kernel<<<NBLK_B, 256>>>(w2, noise, out);
    rescue_kernel<<<MAXR, 256>>>(x, w1, w2, noise, out);
    finalize_kernel<<<1, 256>>>(out);
}

// round 13
// speedup vs baseline: 1.2514x; 1.2514x over previous
#include <cuda_runtime.h>
#include <cuda_bf16.h>
#include <cstdint>

#define TOKENS 32768
#define DMODEL 4096
#define NEXP   64
#define BM     128
#define BK     32
#define XPITCH 132               // xs row pitch: 16B-aligned rows, conflict-free LDS.128
#define WPITCH 136               // wd row pitch (128 dup'd floats + 8 pad), 16B-aligned
#define NSLAB  (DMODEL / BK)     // 128
#define NBLK_B (TOKENS / 256)    // 128 blocks in the gate kernel
#define MAXR   256               // rescue list capacity
#define EPS_MARGIN 2e-4f         // rescue threshold on noisy top1-top2 margin

// Scratch (no allocations allowed)
__device__ float g_h[TOKENS * NEXP];
__device__ float g_imp[NBLK_B * NEXP];
__device__ int   g_load[NBLK_B * NEXP];
__device__ int   g_rescue_cnt;
__device__ int   g_rescue_list[MAXR];
__device__ int   g_load_delta[NEXP];

// ---- packed f32x2 helpers (FFMA2 — only reachable via PTX fma.rn.f32x2) ----
static __device__ __forceinline__ void unpack2(unsigned long long v, float& lo, float& hi) {
    asm("mov.b64 {%0, %1}, %2;" : "=f"(lo), "=f"(hi) : "l"(v));
}
static __device__ __forceinline__ void ffma2(unsigned long long& d,
                                             unsigned long long a,
                                             unsigned long long b) {
    asm("fma.rn.f32x2 %0, %1, %2, %0;" : "+l"(d) : "l"(a), "l"(b));
}

// ============================================================================
// Kernel A: h = tanh(x @ w1^T)   [32768,4096] x [64,4096]^T -> [32768,64]
//
// 256 threads/CTA, tile 128 tokens x 64 experts, BK=32, 2 CTAs/SM.
// acc layout = (token-pair, expert): A-operand (two adjacent tokens) comes
// packed straight from xs; B-operand comes packed from wd, where w was stored
// DUPLICATED at staging time. Zero packing MOVs in the inner loop:
//   per k per warp: 1 LDS.128 (A, conflict-free) + 4 LDS.128 (B, warp-uniform
//   broadcast) + 16 FFMA2  -> 21 issue slots, 8 LSU wavefronts.
//   lane -> tokens lane*4..lane*4+3 (2 pairs); warp -> experts warp*8..+7.
// ============================================================================
__global__ void __launch_bounds__(256, 2)
gemm1_tanh(const float* __restrict__ x, const float* __restrict__ w1) {
    __shared__ __align__(16) float xs[BK][XPITCH];  // xs[k][token]
    __shared__ __align__(16) float wd[BK][WPITCH];  // wd[k][2e]=wd[k][2e+1]=w1[e][k]

    const int tid  = threadIdx.x;
    const int lane = tid & 31;
    const int warp = tid >> 5;
    const int bm   = blockIdx.x * BM;
    const int e0   = warp * 8;             // experts e0..e0+7

    // rescue-state reset (gate runs strictly after gemm1 in stream order)
    if (blockIdx.x == 0) {
        if (tid == 0) g_rescue_cnt = 0;
        if (tid < NEXP) g_load_delta[tid] = 0;
    }

    unsigned long long acc[2][8];          // [token-pair][expert]
#pragma unroll
    for (int p = 0; p < 2; p++)
#pragma unroll
        for (int e = 0; e < 8; e++) acc[p][e] = 0ull;

    // staging coords: thread -> token pair (2tp, 2tp+1) and expert row `tp`,
    // k-chunk slots kc and kc+4 (float4 each) covering the 32-wide slab.
    const int tp = tid >> 2;               // 0..63
    const int kc = tid & 3;                // chunk slot

    // ---- prologue: load slab 0 ----
    float4 xA[2], xB[2], wv[2];
#pragma unroll
    for (int c = 0; c < 2; c++) {
        const int kb = (kc + 4 * c) * 4;
        xA[c] = *reinterpret_cast<const float4*>(&x[(size_t)(bm + 2 * tp) * DMODEL + kb]);
        xB[c] = *reinterpret_cast<const float4*>(&x[(size_t)(bm + 2 * tp + 1) * DMODEL + kb]);
        wv[c] = *reinterpret_cast<const float4*>(&w1[(size_t)tp * DMODEL + kb]);
    }

#pragma unroll 1
    for (int sl = 0; sl < NSLAB; sl++) {
        if (sl) __syncthreads();           // all warps done reading previous slab

        // stage x (token-pair STS.64) and w (duplicated STS.64)
#pragma unroll
        for (int c = 0; c < 2; c++) {
            const int kb = (kc + 4 * c) * 4;
            const float xa[4] = { xA[c].x, xA[c].y, xA[c].z, xA[c].w };
            const float xb[4] = { xB[c].x, xB[c].y, xB[c].z, xB[c].w };
            const float wf[4] = { wv[c].x, wv[c].y, wv[c].z, wv[c].w };
#pragma unroll
            for (int j = 0; j < 4; j++) {
                *reinterpret_cast<float2*>(&xs[kb + j][2 * tp]) = make_float2(xa[j], xb[j]);
                *reinterpret_cast<float2*>(&wd[kb + j][2 * tp]) = make_float2(wf[j], wf[j]);
            }
        }
        __syncthreads();

        // prefetch next slab (overlaps compute below)
        if (sl + 1 < NSLAB) {
            const int kk = (sl + 1) * BK;
#pragma unroll
            for (int c = 0; c < 2; c++) {
                const int kb = kk + (kc + 4 * c) * 4;
                xA[c] = *reinterpret_cast<const float4*>(&x[(size_t)(bm + 2 * tp) * DMODEL + kb]);
                xB[c] = *reinterpret_cast<const float4*>(&x[(size_t)(bm + 2 * tp + 1) * DMODEL + kb]);
                wv[c] = *reinterpret_cast<const float4*>(&w1[(size_t)tp * DMODEL + kb]);
            }
        }

#pragma unroll
        for (int k = 0; k < BK; k++) {
            // A: 4 tokens = 2 ready f32x2 pairs, one conflict-free LDS.128
            const ulonglong2 xp = *reinterpret_cast<const ulonglong2*>(&xs[k][lane * 4]);
            // B: 8 ready dup-packs, 4 warp-uniform LDS.128
            const ulonglong2 wA = *reinterpret_cast<const ulonglong2*>(&wd[k][e0 * 2]);
            const ulonglong2 wB = *reinterpret_cast<const ulonglong2*>(&wd[k][e0 * 2 + 4]);
            const ulonglong2 wC = *reinterpret_cast<const ulonglong2*>(&wd[k][e0 * 2 + 8]);
            const ulonglong2 wD = *reinterpret_cast<const ulonglong2*>(&wd[k][e0 * 2 + 12]);
            ffma2(acc[0][0], xp.x, wA.x); ffma2(acc[0][1], xp.x, wA.y);
            ffma2(acc[0][2], xp.x, wB.x); ffma2(acc[0][3], xp.x, wB.y);
            ffma2(acc[0][4], xp.x, wC.x); ffma2(acc[0][5], xp.x, wC.y);
            ffma2(acc[0][6], xp.x, wD.x); ffma2(acc[0][7], xp.x, wD.y);
            ffma2(acc[1][0], xp.y, wA.x); ffma2(acc[1][1], xp.y, wA.y);
            ffma2(acc[1][2], xp.y, wB.x); ffma2(acc[1][3], xp.y, wB.y);
            ffma2(acc[1][4], xp.y, wC.x); ffma2(acc[1][5], xp.y, wC.y);
            ffma2(acc[1][6], xp.y, wD.x); ffma2(acc[1][7], xp.y, wD.y);
        }
    }

    // ---- epilogue: tanh + store 4 tokens x 8 experts ----
#pragma unroll
    for (int p = 0; p < 2; p++) {
        float lo[8], hi[8];
#pragma unroll
        for (int e = 0; e < 8; e++) unpack2(acc[p][e], lo[e], hi[e]);
        const int t0 = bm + lane * 4 + 2 * p;   // acc.lo = token t0, acc.hi = t0+1
        float* d0 = &g_h[(size_t)t0 * NEXP + e0];
        float* d1 = d0 + NEXP;
        *reinterpret_cast<float4*>(d0) =
            make_float4(tanhf(lo[0]), tanhf(lo[1]), tanhf(lo[2]), tanhf(lo[3]));
        *reinterpret_cast<float4*>(d0 + 4) =
            make_float4(tanhf(lo[4]), tanhf(lo[5]), tanhf(lo[6]), tanhf(lo[7]));
        *reinterpret_cast<float4*>(d1) =
            make_float4(tanhf(hi[0]), tanhf(hi[1]), tanhf(hi[2]), tanhf(hi[3]));
        *reinterpret_cast<float4*>(d1 + 4) =
            make_float4(tanhf(hi[4]), tanhf(hi[5]), tanhf(hi[6]), tanhf(hi[7]));
    }
}

// ============================================================================
// Kernel B: logits = h @ w2^T; softmax; argmax(logits+noise); near-tie tokens
// flagged for fp64 rescue; deterministic block partials (no float atomics).
// ============================================================================
__global__ void __launch_bounds__(256)
gate_kernel(const float* __restrict__ w2, const float* __restrict__ noise,
            float* __restrict__ out) {
    __shared__ float w2s[NEXP][NEXP];
    __shared__ float s_imp[8][NEXP];
    __shared__ int   s_load[NEXP];

    const int tid  = threadIdx.x;
    const int warp = tid >> 5;

    for (int i = tid; i < NEXP * NEXP; i += 256) w2s[i >> 6][i & 63] = w2[i];
    if (tid < NEXP) s_load[tid] = 0;
    __syncthreads();

    const int t = blockIdx.x * 256 + tid;

    float l[NEXP];
#pragma unroll
    for (int e = 0; e < NEXP; e++) l[e] = 0.f;

    const float4* hrow = reinterpret_cast<const float4*>(&g_h[(size_t)t * NEXP]);
#pragma unroll 2
    for (int j4 = 0; j4 < 16; j4++) {
        float4 hv = hrow[j4];
#pragma unroll
        for (int e = 0; e < NEXP; e++) {
            l[e] += hv.x * w2s[e][4 * j4 + 0] + hv.y * w2s[e][4 * j4 + 1] +
                    hv.z * w2s[e][4 * j4 + 2] + hv.w * w2s[e][4 * j4 + 3];
        }
    }

    float maxl = l[0];
#pragma unroll
    for (int e = 1; e < NEXP; e++) maxl = fmaxf(maxl, l[e]);

    // argmax of logits + gumbel noise, tracking top-2 margin for rescue
    const float4* nrow = reinterpret_cast<const float4*>(&noise[(size_t)t * NEXP]);
    float best = -3.402823466e38f, second = -3.402823466e38f;
    int   bi   = 0;
#pragma unroll
    for (int e4 = 0; e4 < 16; e4++) {
        float4 nv = nrow[e4];
        float v;
#define STEP(COMP, OFF)                                                        \
        v = l[4 * e4 + OFF] + nv.COMP;                                         \
        if (v > best) { second = best; best = v; bi = 4 * e4 + OFF; }          \
        else if (v > second) { second = v; }
        STEP(x, 0) STEP(y, 1) STEP(z, 2) STEP(w, 3)
#undef STEP
    }
    if (best - second < EPS_MARGIN) {
        int idx = atomicAdd(&g_rescue_cnt, 1);
        if (idx < MAXR) g_rescue_list[idx] = t;
    }

    float Z = 0.f;
#pragma unroll
    for (int e = 0; e < NEXP; e++) Z += expf(l[e] - maxl);
    const float inv = 1.0f / Z;

#pragma unroll
    for (int e = 0; e < NEXP; e++) {
        float v = expf(l[e] - maxl) * inv;
        v += __shfl_xor_sync(0xffffffffu, v, 16);
        v += __shfl_xor_sync(0xffffffffu, v, 8);
        v += __shfl_xor_sync(0xffffffffu, v, 4);
        v += __shfl_xor_sync(0xffffffffu, v, 2);
        v += __shfl_xor_sync(0xffffffffu, v, 1);
        if ((tid & 31) == 0) s_imp[warp][e] = v;
    }

    atomicAdd(&s_load[bi], 1);   // integer atomics: deterministic

    out[t]          = (float)bi;
    out[TOKENS + t] = best;

    __syncthreads();
    if (tid < NEXP) {
        float s = 0.f;
#pragma unroll
        for (int w = 0; w < 8; w++) s += s_imp[w][tid];
        g_imp[blockIdx.x * NEXP + tid]  = s;
        g_load[blockIdx.x * NEXP + tid] = s_load[tid];
    }
}

// ============================================================================
// Rescue: recompute flagged tokens' gate in fp64 straight from inputs,
// patch indices/scores, accumulate integer load deltas. Deterministic.
// ============================================================================
__global__ void __launch_bounds__(256)
rescue_kernel(const float* __restrict__ x, const float* __restrict__ w1,
              const float* __restrict__ w2, const float* __restrict__ noise,
              float* __restrict__ out) {
    int cnt = g_rescue_cnt;
    if (cnt > MAXR) cnt = MAXR;
    if ((int)blockIdx.x >= cnt) return;
    const int t   = g_rescue_list[blockIdx.x];
    const int tid = threadIdx.x;
    const int j   = tid >> 2;     // expert for layer-1 row
    const int q   = tid & 3;      // k-quarter

    __shared__ double pz[NEXP][4];
    __shared__ double hs[NEXP];
    __shared__ double lv[NEXP];

    const float* xr = x + (size_t)t * DMODEL;
    const float* wr = w1 + (size_t)j * DMODEL;
    double partial = 0.0;
    const int k0 = q * (DMODEL / 4);
#pragma unroll 4
    for (int k = k0; k < k0 + DMODEL / 4; k++)
        partial += (double)xr[k] * (double)wr[k];
    pz[j][q] = partial;
    __syncthreads();

    if (q == 0) {
        double z = ((pz[j][0] + pz[j][1]) + pz[j][2]) + pz[j][3];
        hs[j] = tanh(z);
    }
    __syncthreads();

    if (tid < NEXP) {
        double s = 0.0;
        for (int jj = 0; jj < NEXP; jj++) s += hs[jj] * (double)w2[tid * NEXP + jj];
        lv[tid] = s + (double)noise[(size_t)t * NEXP + tid];
    }
    __syncthreads();

    if (tid == 0) {
        double bv = lv[0];
        int bi = 0;
        for (int e = 1; e < NEXP; e++)
            if (lv[e] > bv) { bv = lv[e]; bi = e; }
        const int old = (int)out[t];
        if (old != bi) {
            atomicAdd(&g_load_delta[old], -1);
            atomicAdd(&g_load_delta[bi], 1);
            out[t] = (float)bi;
        }
        out[TOKENS + t] = (float)bv;
    }
}

// ============================================================================
// Kernel C: finalize — 256 threads, fixed-order 2-stage reduction
// (4 partials of 32 blocks each, then fixed combine) -> deterministic.
// ============================================================================
__global__ void __launch_bounds__(256)
finalize_kernel(float* __restrict__ out) {
    __shared__ float pimp[4][NEXP];
    __shared__ int   pld[4][NEXP];
    __shared__ float red[NEXP];

    const int tid = threadIdx.x;
    const int e   = tid & 63;
    const int q   = tid >> 6;     // 0..3

    float s  = 0.f;
    int   ld = 0;
    for (int b = q * 32; b < q * 32 + 32; b++) {
        s  += g_imp[b * NEXP + e];
        ld += g_load[b * NEXP + e];
    }
    pimp[q][e] = s;
    pld[q][e]  = ld;
    __syncthreads();

    if (tid < NEXP) {
        const float si = ((pimp[0][tid] + pimp[1][tid]) + pimp[2][tid]) + pimp[3][tid];
        const int   li = pld[0][tid] + pld[1][tid] + pld[2][tid] + pld[3][tid]
                         + g_load_delta[tid];
        const float imp_mean  = si * (1.0f / TOKENS);
        const float load_mean = (float)li * (1.0f / TOKENS);
        out[2 * TOKENS + 1 + tid]        = load_mean;
        out[2 * TOKENS + 1 + NEXP + tid] = imp_mean;
        red[tid] = imp_mean * load_mean;
    }
    __syncthreads();
    if (tid == 0) {
        float a = 0.f;
        for (int i = 0; i < NEXP; i++) a += red[i];
        out[2 * TOKENS] = (float)NEXP * a * 0.1f;
    }
}

extern "C" void kernel_launch(void* const* d_in, const int* in_sizes, int n_in,
                              void* d_out, int out_size) {
    const float* x     = (const float*)d_in[0];
    const float* w1    = (const float*)d_in[1];
    const float* w2    = (const float*)d_in[2];
    const float* noise = (const float*)d_in[3];
    float* out = (float*)d_out;

    gemm1_tanh<<<TOKENS / BM, 256>>>(x, w1);
    gate_kernel<<<NBLK_B, 256>>>(w2, noise, out);
    rescue_kernel<<<MAXR, 256>>>(x, w1, w2, noise, out);
    finalize_kernel<<<1, 256>>>(out);
}